// round 7
// baseline (speedup 1.0000x reference)
#include <cuda_runtime.h>

// Problem dims (fixed)
#define T_  512
#define B_  256
#define F_  512
#define H_  128
#define G4_ 512   // 4*H
#define A_  8
#define MH_ 64

// Scratch (allocation-free rule: __device__ globals)
__device__ float g_xgates[(size_t)T_ * B_ * G4_];  // pre-computed x @ W_ih^T + biases
__device__ float g_hseq[(size_t)T_ * B_ * H_];     // per-step hidden states

// ---------------------------------------------------------------------------
// Packed fp32x2 helpers (Blackwell FFMA2 path — only reachable via PTX)
// ---------------------------------------------------------------------------
__device__ __forceinline__ void ffma2(unsigned long long& d,
                                      unsigned long long a,
                                      unsigned long long b) {
    asm("fma.rn.f32x2 %0, %1, %2, %0;" : "+l"(d) : "l"(a), "l"(b));
}
__device__ __forceinline__ unsigned long long addf2(unsigned long long a,
                                                    unsigned long long b) {
    unsigned long long r;
    asm("add.rn.f32x2 %0, %1, %2;" : "=l"(r) : "l"(a), "l"(b));
    return r;
}
__device__ __forceinline__ float lo_f(unsigned long long p) {
    return __uint_as_float((unsigned)(p & 0xffffffffull));
}
__device__ __forceinline__ float hi_f(unsigned long long p) {
    return __uint_as_float((unsigned)(p >> 32));
}
__device__ __forceinline__ unsigned long long dup2(float x) {
    unsigned u = __float_as_uint(x);
    return ((unsigned long long)u << 32) | (unsigned long long)u;
}

// ---------------------------------------------------------------------------
// Fast activations (fp32, ~1e-6 rel err)
// ---------------------------------------------------------------------------
__device__ __forceinline__ float sigm_f(float x) {
    return 1.0f / (1.0f + __expf(-x));
}
__device__ __forceinline__ float tanh_f(float x) {
    float e = __expf(2.0f * x);
    return 1.0f - 2.0f / (e + 1.0f);
}

// ---------------------------------------------------------------------------
// Kernel 1: xgates = X[131072,512] @ W_ih^T[512,512] + (b_ih + b_hh)
// FFMA2 SGEMM: 128x128x16 tiles, 256 threads.
// Accumulators pack the M dimension: acc[i][j] = (row 2i, row 2i+1) pair.
// A tile k-major (pairs contiguous); B tile stored as DUPLICATED float2 (b,b)
// so the packed multiplicand needs no per-k repacking. B columns are swizzled
// (thread tn owns cols {16j + tn}) to make the LDS.64 pattern conflict-free.
// 2-stage double buffer, one __syncthreads per k-tile.
// ---------------------------------------------------------------------------
#define KT 16
__global__ __launch_bounds__(256, 2)
void gemm_xw_kernel(const float* __restrict__ X,
                    const float* __restrict__ Wih,
                    const float* __restrict__ bih,
                    const float* __restrict__ bhh)
{
    __shared__ float              As [2][KT * 128];   // As[s][k*128 + m]
    __shared__ unsigned long long Bsd[2][KT * 128];   // dup pairs: Bsd[s][k*128 + g]

    const int tid = threadIdx.x;
    const int bm  = blockIdx.x >> 2;
    const int bn  = blockIdx.x & 3;
    const int m0  = bm * 128;
    const int g0  = bn * 128;

    const int tm = tid >> 4;   // 0..15 (8 m-rows each)
    const int tn = tid & 15;   // 0..15 (cols 16j+tn)

    // loader: each thread loads 8 consecutive k of one row for A and B
    const int lrow = tid >> 1;        // 0..127
    const int lk   = (tid & 1) * 8;   // 0 or 8

    const float* Xp = X   + (size_t)(m0 + lrow) * F_ + lk;
    const float* Wp = Wih + (size_t)(g0 + lrow) * F_ + lk;

    unsigned long long acc[4][8];
#pragma unroll
    for (int i = 0; i < 4; i++)
#pragma unroll
        for (int j = 0; j < 8; j++) acc[i][j] = 0ull;

    float bias[8];
#pragma unroll
    for (int j = 0; j < 8; j++) {
        int g = g0 + 16 * j + tn;
        bias[j] = bih[g] + bhh[g];
    }

    // prologue: load tile 0 and stage it
    float4 ra0 = *reinterpret_cast<const float4*>(Xp);
    float4 ra1 = *reinterpret_cast<const float4*>(Xp + 4);
    float4 rb0 = *reinterpret_cast<const float4*>(Wp);
    float4 rb1 = *reinterpret_cast<const float4*>(Wp + 4);
    {
        float av[8] = {ra0.x, ra0.y, ra0.z, ra0.w, ra1.x, ra1.y, ra1.z, ra1.w};
        float bv[8] = {rb0.x, rb0.y, rb0.z, rb0.w, rb1.x, rb1.y, rb1.z, rb1.w};
#pragma unroll
        for (int q = 0; q < 8; q++) {
            As [0][(lk + q) * 128 + lrow] = av[q];
            Bsd[0][(lk + q) * 128 + lrow] = dup2(bv[q]);
        }
    }
    __syncthreads();

    const int NT = F_ / KT;   // 32 k-tiles
#pragma unroll 1
    for (int kt = 0; kt < NT; kt++) {
        const int cur = kt & 1;

        // prefetch next tile into registers (latency hidden by compute)
        if (kt + 1 < NT) {
            const float* xn = Xp + (kt + 1) * KT;
            const float* wn = Wp + (kt + 1) * KT;
            ra0 = *reinterpret_cast<const float4*>(xn);
            ra1 = *reinterpret_cast<const float4*>(xn + 4);
            rb0 = *reinterpret_cast<const float4*>(wn);
            rb1 = *reinterpret_cast<const float4*>(wn + 4);
        }

        // compute current stage
        const float*              Ac = As [cur];
        const unsigned long long* Bc = Bsd[cur];
#pragma unroll
        for (int k = 0; k < KT; k++) {
            unsigned long long a[4];
            const unsigned long long* arow =
                reinterpret_cast<const unsigned long long*>(Ac + k * 128 + tm * 8);
            a[0] = arow[0]; a[1] = arow[1]; a[2] = arow[2]; a[3] = arow[3];

            unsigned long long b[8];
            const unsigned long long* brow = Bc + k * 128;
#pragma unroll
            for (int j = 0; j < 8; j++) b[j] = brow[j * 16 + tn];

#pragma unroll
            for (int i = 0; i < 4; i++)
#pragma unroll
                for (int j = 0; j < 8; j++)
                    ffma2(acc[i][j], a[i], b[j]);
        }

        // stage next tile
        if (kt + 1 < NT) {
            const int nxt = cur ^ 1;
            float av[8] = {ra0.x, ra0.y, ra0.z, ra0.w, ra1.x, ra1.y, ra1.z, ra1.w};
            float bv[8] = {rb0.x, rb0.y, rb0.z, rb0.w, rb1.x, rb1.y, rb1.z, rb1.w};
#pragma unroll
            for (int q = 0; q < 8; q++) {
                As [nxt][(lk + q) * 128 + lrow] = av[q];
                Bsd[nxt][(lk + q) * 128 + lrow] = dup2(bv[q]);
            }
        }
        __syncthreads();
    }

    // epilogue: unpack pairs, add bias, store
#pragma unroll
    for (int i = 0; i < 4; i++) {
        const size_t mA = (size_t)(m0 + tm * 8 + 2 * i);
        float* rowA = g_xgates + mA * G4_ + g0;
        float* rowB = rowA + G4_;      // row mA+1
#pragma unroll
        for (int j = 0; j < 8; j++) {
            int col = 16 * j + tn;
            rowA[col] = lo_f(acc[i][j]) + bias[j];
            rowB[col] = hi_f(acc[i][j]) + bias[j];
        }
    }
}

// ---------------------------------------------------------------------------
// Kernel 2: persistent masked-LSTM recurrence, FFMA2 packed over K.
// Grid = 128 blocks x 512 threads; block owns batch rows {2*bx, 2*bx+1}.
// W_hh split: cols 0..31 in registers as (k,k+1) pairs, cols 32..127 in smem
// (float4 = 2 pairs, read as ulonglong2). h pairs are naturally contiguous.
//
// Dynamic smem layout (floats):
//   [0     , 49152) Wsm4 : float4[24*512], Wsm4[k4*512+g] = W_hh[g][32+4k4..+3]
//   [49152 , 50176) done_s[1024]  (t-major, 2 rows)
//   [50176 , 50432) h_s[2][128]
//   [50432 , 51456) gs [2][512]
// total = 51456 floats = 205824 bytes
// ---------------------------------------------------------------------------
__global__ __launch_bounds__(512, 1)
void lstm_kernel(const float* __restrict__ done,
                 const float* __restrict__ h0,
                 const float* __restrict__ c0,
                 const float* __restrict__ Whh,
                 float* __restrict__ hT,
                 float* __restrict__ cT)
{
    extern __shared__ float sm[];
    float4*     Wsm4   = reinterpret_cast<float4*>(sm);       // [24*512]
    ulonglong2* Wsm2   = reinterpret_cast<ulonglong2*>(sm);   // same memory
    float*      done_s = sm + 49152;                          // [1024]
    float*      h_s    = sm + 50176;                          // [2][128]
    float*      gs     = sm + 50432;                          // [2][512]

    const int tid = threadIdx.x;
    const int g   = tid;               // gate row this thread computes (0..511)
    const int b0  = blockIdx.x * 2;

    // Register part of W_hh: W_hh[g][0:32] as 16 packed pairs
    unsigned long long Wreg2[16];
    {
        const ulonglong2* wrow2 = reinterpret_cast<const ulonglong2*>(Whh + (size_t)g * H_);
#pragma unroll
        for (int k4 = 0; k4 < 8; k4++) {
            ulonglong2 v = wrow2[k4];
            Wreg2[2 * k4 + 0] = v.x;
            Wreg2[2 * k4 + 1] = v.y;
        }
        // Smem part: cols 32..127 of this thread's gate row
        const float4* wrow4 = reinterpret_cast<const float4*>(Whh + (size_t)g * H_);
#pragma unroll
        for (int k4 = 0; k4 < 24; k4++)
            Wsm4[k4 * 512 + g] = wrow4[8 + k4];
    }
    // done-mask preload for this block's 2 batch rows
    for (int idx = tid; idx < 2 * T_; idx += 512) {
        int t = idx >> 1, bi2 = idx & 1;
        done_s[idx] = done[(size_t)t * B_ + b0 + bi2];
    }

    // Per-(b,j) state in registers of threads 0..255
    const int bi = tid >> 7;    // 0/1  (valid for tid<256)
    const int j  = tid & 127;
    float creg = 0.0f;
    if (tid < 256) {
        float hreg = h0[(size_t)(b0 + bi) * H_ + j];
        creg = c0[(size_t)(b0 + bi) * H_ + j];
        float m = 1.0f - done_s[bi];
        creg *= m;
        h_s[bi * 128 + j] = hreg * m;
    }
    __syncthreads();

    const ulonglong2* h0p = reinterpret_cast<const ulonglong2*>(h_s);        // 32 entries
    const ulonglong2* h1p = reinterpret_cast<const ulonglong2*>(h_s + 128);

    float hfin = 0.0f;

#pragma unroll 1
    for (int t = 0; t < T_; t++) {
        // ---- Step A: gates[b][g] = xgate + <W_hh[g,:], h[b,:]>  (packed K)
        {
            const float* xg = g_xgates + ((size_t)t * B_ + b0) * G4_;
            float xg0 = xg[g];
            float xg1 = xg[G4_ + g];

            unsigned long long acc0a = 0ull, acc0b = 0ull;
            unsigned long long acc1a = 0ull, acc1b = 0ull;

            // register part (cols 0..31)
#pragma unroll
            for (int k4 = 0; k4 < 8; k4++) {
                ulonglong2 ha = h0p[k4];
                ulonglong2 hb = h1p[k4];
                ffma2(acc0a, Wreg2[2 * k4 + 0], ha.x);
                ffma2(acc0b, Wreg2[2 * k4 + 1], ha.y);
                ffma2(acc1a, Wreg2[2 * k4 + 0], hb.x);
                ffma2(acc1b, Wreg2[2 * k4 + 1], hb.y);
            }
            // smem part (cols 32..127)
#pragma unroll 4
            for (int k4 = 0; k4 < 24; k4++) {
                ulonglong2 w  = Wsm2[k4 * 512 + g];
                ulonglong2 ha = h0p[8 + k4];
                ulonglong2 hb = h1p[8 + k4];
                ffma2(acc0a, w.x, ha.x);
                ffma2(acc0b, w.y, ha.y);
                ffma2(acc1a, w.x, hb.x);
                ffma2(acc1b, w.y, hb.y);
            }
            unsigned long long s0 = addf2(acc0a, acc0b);
            unsigned long long s1 = addf2(acc1a, acc1b);
            gs[g]       = lo_f(s0) + hi_f(s0) + xg0;
            gs[512 + g] = lo_f(s1) + hi_f(s1) + xg1;
        }
        __syncthreads();

        // ---- Step B: nonlinearities + state update + mask-for-(t+1) + publish
        if (tid < 256) {
            float gi = gs[bi * 512 +        j];
            float gf = gs[bi * 512 + 128 + j];
            float gg = gs[bi * 512 + 256 + j];
            float go = gs[bi * 512 + 384 + j];
            float iv = sigm_f(gi);
            float fv = sigm_f(gf);
            float gv = tanh_f(gg);
            float ov = sigm_f(go);
            creg = fmaf(fv, creg, iv * gv);
            float hv = ov * tanh_f(creg);
            g_hseq[((size_t)t * B_ + b0 + bi) * H_ + j] = hv;
            if (t + 1 < T_) {
                float m = 1.0f - done_s[(t + 1) * 2 + bi];
                creg *= m;
                h_s[bi * 128 + j] = hv * m;
            } else {
                hfin = hv;
            }
        }
        __syncthreads();
    }

    if (tid < 256) {
        hT[(size_t)(b0 + bi) * H_ + j] = hfin;
        cT[(size_t)(b0 + bi) * H_ + j] = creg;
    }
}

// ---------------------------------------------------------------------------
// Kernel 3: heads. Block = 256 threads = 256 rows of hseq. (unchanged)
// ---------------------------------------------------------------------------
__global__ __launch_bounds__(256, 1)
void heads_kernel(const float* __restrict__ Wp1, const float* __restrict__ bp1,
                  const float* __restrict__ Wp2, const float* __restrict__ bp2,
                  const float* __restrict__ Wv1, const float* __restrict__ bv1,
                  const float* __restrict__ Wv2, const float* __restrict__ bv2,
                  float* __restrict__ out)
{
    extern __shared__ float sm[];
    float* h_s  = sm;            // [256][129]
    float* wp1  = sm + 33024;    // [8192]
    float* wv1  = sm + 41216;    // [8192]
    float* wp2  = sm + 49408;    // [512]
    float* wv2  = sm + 49920;    // [64]
    float* sbp1 = sm + 49984;    // [64]
    float* sbv1 = sm + 50048;    // [64]

    const int tid = threadIdx.x;
    const size_t row0 = (size_t)blockIdx.x * 256;

    for (int idx = tid; idx < 256 * 32; idx += 256) {
        int r  = idx >> 5;
        int c4 = idx & 31;
        float4 v = reinterpret_cast<const float4*>(g_hseq + (row0 + r) * H_)[c4];
        float* dst = h_s + r * 129 + c4 * 4;
        dst[0] = v.x; dst[1] = v.y; dst[2] = v.z; dst[3] = v.w;
    }
    for (int idx = tid; idx < H_ * MH_; idx += 256) {
        wp1[idx] = Wp1[idx];
        wv1[idx] = Wv1[idx];
    }
    for (int idx = tid; idx < MH_ * A_; idx += 256) wp2[idx] = Wp2[idx];
    if (tid < 64) {
        wv2[tid]  = Wv2[tid];
        sbp1[tid] = bp1[tid];
        sbv1[tid] = bv1[tid];
    }
    __syncthreads();

    float ap[64], av[64];
#pragma unroll
    for (int i = 0; i < 64; i++) { ap[i] = 0.0f; av[i] = 0.0f; }

    const float*  hrow = h_s + tid * 129;
    const float4* wp1v = reinterpret_cast<const float4*>(wp1);
    const float4* wv1v = reinterpret_cast<const float4*>(wv1);

#pragma unroll 1
    for (int k = 0; k < H_; k++) {
        float hk = hrow[k];
#pragma unroll
        for (int m4 = 0; m4 < 16; m4++) {
            float4 wp = wp1v[k * 16 + m4];
            float4 wv = wv1v[k * 16 + m4];
            ap[m4 * 4 + 0] = fmaf(hk, wp.x, ap[m4 * 4 + 0]);
            ap[m4 * 4 + 1] = fmaf(hk, wp.y, ap[m4 * 4 + 1]);
            ap[m4 * 4 + 2] = fmaf(hk, wp.z, ap[m4 * 4 + 2]);
            ap[m4 * 4 + 3] = fmaf(hk, wp.w, ap[m4 * 4 + 3]);
            av[m4 * 4 + 0] = fmaf(hk, wv.x, av[m4 * 4 + 0]);
            av[m4 * 4 + 1] = fmaf(hk, wv.y, av[m4 * 4 + 1]);
            av[m4 * 4 + 2] = fmaf(hk, wv.z, av[m4 * 4 + 2]);
            av[m4 * 4 + 3] = fmaf(hk, wv.w, av[m4 * 4 + 3]);
        }
    }

    float lg[8];
#pragma unroll
    for (int a = 0; a < 8; a++) lg[a] = bp2[a];
    float v = bv2[0];

#pragma unroll
    for (int mh = 0; mh < 64; mh++) {
        float tp = tanh_f(ap[mh] + sbp1[mh]);
        float tv = tanh_f(av[mh] + sbv1[mh]);
        v = fmaf(tv, wv2[mh], v);
#pragma unroll
        for (int a = 0; a < 8; a++)
            lg[a] = fmaf(tp, wp2[mh * 8 + a], lg[a]);
    }

    float* orow = out + (row0 + tid) * 9;
#pragma unroll
    for (int a = 0; a < 8; a++) orow[a] = lg[a];
    orow[8] = v;
}

// ---------------------------------------------------------------------------
// Launch
// ---------------------------------------------------------------------------
extern "C" void kernel_launch(void* const* d_in, const int* in_sizes, int n_in,
                              void* d_out, int out_size)
{
    (void)in_sizes; (void)n_in; (void)out_size;

    const float* x    = (const float*)d_in[0];
    const float* done = (const float*)d_in[1];
    const float* h0   = (const float*)d_in[2];
    const float* c0   = (const float*)d_in[3];
    const float* Wih  = (const float*)d_in[4];
    const float* Whh  = (const float*)d_in[5];
    const float* bih  = (const float*)d_in[6];
    const float* bhh  = (const float*)d_in[7];
    const float* Wp1  = (const float*)d_in[8];
    const float* bp1  = (const float*)d_in[9];
    const float* Wp2  = (const float*)d_in[10];
    const float* bp2  = (const float*)d_in[11];
    const float* Wv1  = (const float*)d_in[12];
    const float* bv1  = (const float*)d_in[13];
    const float* Wv2  = (const float*)d_in[14];
    const float* bv2  = (const float*)d_in[15];

    float* out = (float*)d_out;
    float* hT  = out + (size_t)T_ * B_ * (A_ + 1);   // after [T*B, 9]
    float* cT  = hT + (size_t)B_ * H_;

    const int lstm_smem  = 51456 * 4;   // 205824 B
    const int heads_smem = 50112 * 4;   // 200448 B
    cudaFuncSetAttribute(lstm_kernel,  cudaFuncAttributeMaxDynamicSharedMemorySize, lstm_smem);
    cudaFuncSetAttribute(heads_kernel, cudaFuncAttributeMaxDynamicSharedMemorySize, heads_smem);

    // 1) input projection: 1024 m-tiles x 4 n-tiles (FFMA2)
    gemm_xw_kernel<<<4096, 256>>>(x, Wih, bih, bhh);
    // 2) recurrence: 128 persistent blocks (2 batch rows each, FFMA2)
    lstm_kernel<<<128, 512, lstm_smem>>>(done, h0, c0, Whh, hT, cT);
    // 3) heads: 512 blocks x 256 rows
    heads_kernel<<<512, 256, heads_smem>>>(Wp1, bp1, Wp2, bp2, Wv1, bv1, Wv2, bv2, out);
}

// round 10
// speedup vs baseline: 1.6550x; 1.6550x over previous
#include <cuda_runtime.h>

// Problem dims (fixed)
#define T_  512
#define B_  256
#define F_  512
#define H_  128
#define G4_ 512   // 4*H
#define A_  8
#define MH_ 64

// Scratch (allocation-free rule: __device__ globals)
__device__ float g_xgates[(size_t)T_ * B_ * G4_];  // x @ W_ih^T + biases
__device__ float g_hseq[(size_t)T_ * B_ * H_];     // per-step hidden states

// ---------------------------------------------------------------------------
// Fast activations (fp32, ~1e-6 rel err)
// ---------------------------------------------------------------------------
__device__ __forceinline__ float sigm_f(float x) {
    return 1.0f / (1.0f + __expf(-x));
}
__device__ __forceinline__ float tanh_f(float x) {
    float e = __expf(2.0f * x);
    return 1.0f - 2.0f / (e + 1.0f);
}

// ---------------------------------------------------------------------------
// Kernel 1: xgates = X[131072,512] @ W_ih^T[512,512] + (b_ih + b_hh)
// 128x128x16 tiled SGEMM, 256 threads, 8x8 microtile — now double-buffered:
// one __syncthreads per k-tile, global->register prefetch overlaps compute.
// ---------------------------------------------------------------------------
#define KT 16
__global__ __launch_bounds__(256, 2)
void gemm_xw_kernel(const float* __restrict__ X,
                    const float* __restrict__ Wih,
                    const float* __restrict__ bih,
                    const float* __restrict__ bhh)
{
    __shared__ float As[2][KT * 128];   // As[s][k*128 + m]
    __shared__ float Bs[2][KT * 128];   // Bs[s][k*128 + g]

    const int tid = threadIdx.x;
    const int bm  = blockIdx.x >> 2;
    const int bn  = blockIdx.x & 3;
    const int m0  = bm * 128;
    const int g0  = bn * 128;

    const int tm = tid >> 4;   // 0..15 (8 m-rows)
    const int tn = tid & 15;   // 0..15 (8 g-cols)

    // loader: each thread loads 8 consecutive k of one row (A and B)
    const int lrow = tid >> 1;        // 0..127
    const int lk   = (tid & 1) * 8;   // 0 or 8

    const float* Xp = X   + (size_t)(m0 + lrow) * F_ + lk;
    const float* Wp = Wih + (size_t)(g0 + lrow) * F_ + lk;

    float acc[8][8];
#pragma unroll
    for (int i = 0; i < 8; i++)
#pragma unroll
        for (int j = 0; j < 8; j++) acc[i][j] = 0.0f;

    float bias[8];
#pragma unroll
    for (int j = 0; j < 8; j++) {
        int g = g0 + tn * 8 + j;
        bias[j] = bih[g] + bhh[g];
    }

    // prologue: tile 0 -> stage 0
    float4 ra0 = *reinterpret_cast<const float4*>(Xp);
    float4 ra1 = *reinterpret_cast<const float4*>(Xp + 4);
    float4 rb0 = *reinterpret_cast<const float4*>(Wp);
    float4 rb1 = *reinterpret_cast<const float4*>(Wp + 4);
    {
        float av[8] = {ra0.x, ra0.y, ra0.z, ra0.w, ra1.x, ra1.y, ra1.z, ra1.w};
        float bv[8] = {rb0.x, rb0.y, rb0.z, rb0.w, rb1.x, rb1.y, rb1.z, rb1.w};
#pragma unroll
        for (int q = 0; q < 8; q++) {
            As[0][(lk + q) * 128 + lrow] = av[q];
            Bs[0][(lk + q) * 128 + lrow] = bv[q];
        }
    }
    __syncthreads();

    const int NT = F_ / KT;   // 32
#pragma unroll 1
    for (int kt = 0; kt < NT; kt++) {
        const int cur = kt & 1;

        // prefetch next tile into registers (overlaps compute below)
        if (kt + 1 < NT) {
            const float* xn = Xp + (kt + 1) * KT;
            const float* wn = Wp + (kt + 1) * KT;
            ra0 = *reinterpret_cast<const float4*>(xn);
            ra1 = *reinterpret_cast<const float4*>(xn + 4);
            rb0 = *reinterpret_cast<const float4*>(wn);
            rb1 = *reinterpret_cast<const float4*>(wn + 4);
        }

        const float* Ac = As[cur];
        const float* Bc = Bs[cur];
#pragma unroll
        for (int k = 0; k < KT; k++) {
            float a[8], b[8];
            float4 a0 = *reinterpret_cast<const float4*>(Ac + k * 128 + tm * 8);
            float4 a1 = *reinterpret_cast<const float4*>(Ac + k * 128 + tm * 8 + 4);
            float4 b0 = *reinterpret_cast<const float4*>(Bc + k * 128 + tn * 8);
            float4 b1 = *reinterpret_cast<const float4*>(Bc + k * 128 + tn * 8 + 4);
            a[0]=a0.x; a[1]=a0.y; a[2]=a0.z; a[3]=a0.w; a[4]=a1.x; a[5]=a1.y; a[6]=a1.z; a[7]=a1.w;
            b[0]=b0.x; b[1]=b0.y; b[2]=b0.z; b[3]=b0.w; b[4]=b1.x; b[5]=b1.y; b[6]=b1.z; b[7]=b1.w;
#pragma unroll
            for (int i = 0; i < 8; i++)
#pragma unroll
                for (int j = 0; j < 8; j++)
                    acc[i][j] = fmaf(a[i], b[j], acc[i][j]);
        }

        // stage next tile (writes target the OTHER stage; reads above used cur)
        if (kt + 1 < NT) {
            const int nxt = cur ^ 1;
            float av[8] = {ra0.x, ra0.y, ra0.z, ra0.w, ra1.x, ra1.y, ra1.z, ra1.w};
            float bv[8] = {rb0.x, rb0.y, rb0.z, rb0.w, rb1.x, rb1.y, rb1.z, rb1.w};
#pragma unroll
            for (int q = 0; q < 8; q++) {
                As[nxt][(lk + q) * 128 + lrow] = av[q];
                Bs[nxt][(lk + q) * 128 + lrow] = bv[q];
            }
        }
        __syncthreads();
    }

#pragma unroll
    for (int i = 0; i < 8; i++) {
        int m = m0 + tm * 8 + i;
        float4 o0 = make_float4(acc[i][0] + bias[0], acc[i][1] + bias[1],
                                acc[i][2] + bias[2], acc[i][3] + bias[3]);
        float4 o1 = make_float4(acc[i][4] + bias[4], acc[i][5] + bias[5],
                                acc[i][6] + bias[6], acc[i][7] + bias[7]);
        float* dst = g_xgates + (size_t)m * G4_ + g0 + tn * 8;
        *reinterpret_cast<float4*>(dst)     = o0;
        *reinterpret_cast<float4*>(dst + 4) = o1;
    }
}

// ---------------------------------------------------------------------------
// Kernel 2: persistent masked-LSTM recurrence (R5 structure + xg prefetch).
// Grid = 128 blocks x 512 threads; block owns batch rows {2*bx, 2*bx+1}.
// W_hh split: cols 0..31 in registers, cols 32..127 in smem (float4).
// The g_xgates pair for step t+1 is prefetched at the top of step t so its
// DRAM/L2 latency is hidden behind a full step of FMA work.
//
// Dynamic smem (floats): Wsm4[24*512] | done_s[1024] | h_s[2][128] | gs[2][512]
// total = 51456 floats = 205824 bytes
// ---------------------------------------------------------------------------
__global__ __launch_bounds__(512, 1)
void lstm_kernel(const float* __restrict__ done,
                 const float* __restrict__ h0,
                 const float* __restrict__ c0,
                 const float* __restrict__ Whh,
                 float* __restrict__ hT,
                 float* __restrict__ cT)
{
    extern __shared__ float sm[];
    float4* Wsm4   = reinterpret_cast<float4*>(sm);
    float*  done_s = sm + 49152;
    float*  h_s    = sm + 50176;
    float*  gs     = sm + 50432;

    const int tid = threadIdx.x;
    const int g   = tid;               // gate row (0..511)
    const int b0  = blockIdx.x * 2;

    float Wreg[32];
    {
        const float4* wrow = reinterpret_cast<const float4*>(Whh + (size_t)g * H_);
#pragma unroll
        for (int k4 = 0; k4 < 8; k4++) {
            float4 v = wrow[k4];
            Wreg[k4 * 4 + 0] = v.x;
            Wreg[k4 * 4 + 1] = v.y;
            Wreg[k4 * 4 + 2] = v.z;
            Wreg[k4 * 4 + 3] = v.w;
        }
#pragma unroll
        for (int k4 = 0; k4 < 24; k4++)
            Wsm4[k4 * 512 + g] = wrow[8 + k4];
    }
    for (int idx = tid; idx < 2 * T_; idx += 512) {
        int t = idx >> 1, bi2 = idx & 1;
        done_s[idx] = done[(size_t)t * B_ + b0 + bi2];
    }

    const int bi = tid >> 7;
    const int j  = tid & 127;
    float creg = 0.0f;
    if (tid < 256) {
        float hreg = h0[(size_t)(b0 + bi) * H_ + j];
        creg = c0[(size_t)(b0 + bi) * H_ + j];
        float m = 1.0f - done_s[bi];
        creg *= m;
        h_s[bi * 128 + j] = hreg * m;
    }
    __syncthreads();

    const float4* h0v = reinterpret_cast<const float4*>(h_s);
    const float4* h1v = reinterpret_cast<const float4*>(h_s + 128);

    // xg prefetch state: values for the CURRENT step live in registers.
    const size_t step_stride = (size_t)B_ * G4_;
    const float* xg_base = g_xgates + (size_t)b0 * G4_;
    float xg0 = xg_base[g];
    float xg1 = xg_base[G4_ + g];

    float hfin = 0.0f;

#pragma unroll 1
    for (int t = 0; t < T_; t++) {
        // issue next step's xg loads NOW (consumed one full step later)
        const int tn = (t + 1 < T_) ? (t + 1) : t;
        const float* xn = xg_base + (size_t)tn * step_stride;
        float nx0 = xn[g];
        float nx1 = xn[G4_ + g];

        // ---- Step A: gates[b][g] = xgate + <W_hh[g,:], h[b,:]>
        {
            float acc0 = 0.0f, acc1 = 0.0f, acc0b = 0.0f, acc1b = 0.0f;
#pragma unroll
            for (int k4 = 0; k4 < 8; k4++) {
                float4 ha = h0v[k4];
                float4 hb = h1v[k4];
                acc0  = fmaf(Wreg[4 * k4 + 0], ha.x, acc0);
                acc0b = fmaf(Wreg[4 * k4 + 1], ha.y, acc0b);
                acc0  = fmaf(Wreg[4 * k4 + 2], ha.z, acc0);
                acc0b = fmaf(Wreg[4 * k4 + 3], ha.w, acc0b);
                acc1  = fmaf(Wreg[4 * k4 + 0], hb.x, acc1);
                acc1b = fmaf(Wreg[4 * k4 + 1], hb.y, acc1b);
                acc1  = fmaf(Wreg[4 * k4 + 2], hb.z, acc1);
                acc1b = fmaf(Wreg[4 * k4 + 3], hb.w, acc1b);
            }
#pragma unroll 4
            for (int k4 = 0; k4 < 24; k4++) {
                float4 w  = Wsm4[k4 * 512 + g];
                float4 ha = h0v[8 + k4];
                float4 hb = h1v[8 + k4];
                acc0  = fmaf(w.x, ha.x, acc0);
                acc0b = fmaf(w.y, ha.y, acc0b);
                acc0  = fmaf(w.z, ha.z, acc0);
                acc0b = fmaf(w.w, ha.w, acc0b);
                acc1  = fmaf(w.x, hb.x, acc1);
                acc1b = fmaf(w.y, hb.y, acc1b);
                acc1  = fmaf(w.z, hb.z, acc1);
                acc1b = fmaf(w.w, hb.w, acc1b);
            }
            gs[g]       = acc0 + acc0b + xg0;
            gs[512 + g] = acc1 + acc1b + xg1;
        }
        __syncthreads();

        // rotate prefetched xg into place for the next iteration
        xg0 = nx0;
        xg1 = nx1;

        // ---- Step B: nonlinearities + state update + mask-for-(t+1) + publish
        if (tid < 256) {
            float gi = gs[bi * 512 +        j];
            float gf = gs[bi * 512 + 128 + j];
            float gg = gs[bi * 512 + 256 + j];
            float go = gs[bi * 512 + 384 + j];
            float iv = sigm_f(gi);
            float fv = sigm_f(gf);
            float gv = tanh_f(gg);
            float ov = sigm_f(go);
            creg = fmaf(fv, creg, iv * gv);
            float hv = ov * tanh_f(creg);
            g_hseq[((size_t)t * B_ + b0 + bi) * H_ + j] = hv;
            if (t + 1 < T_) {
                float m = 1.0f - done_s[(t + 1) * 2 + bi];
                creg *= m;
                h_s[bi * 128 + j] = hv * m;
            } else {
                hfin = hv;
            }
        }
        __syncthreads();
    }

    if (tid < 256) {
        hT[(size_t)(b0 + bi) * H_ + j] = hfin;
        cT[(size_t)(b0 + bi) * H_ + j] = creg;
    }
}

// ---------------------------------------------------------------------------
// Kernel 3: heads (R5 version, known good).
// ---------------------------------------------------------------------------
__global__ __launch_bounds__(256, 1)
void heads_kernel(const float* __restrict__ Wp1, const float* __restrict__ bp1,
                  const float* __restrict__ Wp2, const float* __restrict__ bp2,
                  const float* __restrict__ Wv1, const float* __restrict__ bv1,
                  const float* __restrict__ Wv2, const float* __restrict__ bv2,
                  float* __restrict__ out)
{
    extern __shared__ float sm[];
    float* h_s  = sm;            // [256][129]
    float* wp1  = sm + 33024;
    float* wv1  = sm + 41216;
    float* wp2  = sm + 49408;
    float* wv2  = sm + 49920;
    float* sbp1 = sm + 49984;
    float* sbv1 = sm + 50048;

    const int tid = threadIdx.x;
    const size_t row0 = (size_t)blockIdx.x * 256;

    for (int idx = tid; idx < 256 * 32; idx += 256) {
        int r  = idx >> 5;
        int c4 = idx & 31;
        float4 v = reinterpret_cast<const float4*>(g_hseq + (row0 + r) * H_)[c4];
        float* dst = h_s + r * 129 + c4 * 4;
        dst[0] = v.x; dst[1] = v.y; dst[2] = v.z; dst[3] = v.w;
    }
    for (int idx = tid; idx < H_ * MH_; idx += 256) {
        wp1[idx] = Wp1[idx];
        wv1[idx] = Wv1[idx];
    }
    for (int idx = tid; idx < MH_ * A_; idx += 256) wp2[idx] = Wp2[idx];
    if (tid < 64) {
        wv2[tid]  = Wv2[tid];
        sbp1[tid] = bp1[tid];
        sbv1[tid] = bv1[tid];
    }
    __syncthreads();

    float ap[64], av[64];
#pragma unroll
    for (int i = 0; i < 64; i++) { ap[i] = 0.0f; av[i] = 0.0f; }

    const float*  hrow = h_s + tid * 129;
    const float4* wp1v = reinterpret_cast<const float4*>(wp1);
    const float4* wv1v = reinterpret_cast<const float4*>(wv1);

#pragma unroll 1
    for (int k = 0; k < H_; k++) {
        float hk = hrow[k];
#pragma unroll
        for (int m4 = 0; m4 < 16; m4++) {
            float4 wp = wp1v[k * 16 + m4];
            float4 wv = wv1v[k * 16 + m4];
            ap[m4 * 4 + 0] = fmaf(hk, wp.x, ap[m4 * 4 + 0]);
            ap[m4 * 4 + 1] = fmaf(hk, wp.y, ap[m4 * 4 + 1]);
            ap[m4 * 4 + 2] = fmaf(hk, wp.z, ap[m4 * 4 + 2]);
            ap[m4 * 4 + 3] = fmaf(hk, wp.w, ap[m4 * 4 + 3]);
            av[m4 * 4 + 0] = fmaf(hk, wv.x, av[m4 * 4 + 0]);
            av[m4 * 4 + 1] = fmaf(hk, wv.y, av[m4 * 4 + 1]);
            av[m4 * 4 + 2] = fmaf(hk, wv.z, av[m4 * 4 + 2]);
            av[m4 * 4 + 3] = fmaf(hk, wv.w, av[m4 * 4 + 3]);
        }
    }

    float lg[8];
#pragma unroll
    for (int a = 0; a < 8; a++) lg[a] = bp2[a];
    float v = bv2[0];

#pragma unroll
    for (int mh = 0; mh < 64; mh++) {
        float tp = tanh_f(ap[mh] + sbp1[mh]);
        float tv = tanh_f(av[mh] + sbv1[mh]);
        v = fmaf(tv, wv2[mh], v);
#pragma unroll
        for (int a = 0; a < 8; a++)
            lg[a] = fmaf(tp, wp2[mh * 8 + a], lg[a]);
    }

    float* orow = out + (row0 + tid) * 9;
#pragma unroll
    for (int a = 0; a < 8; a++) orow[a] = lg[a];
    orow[8] = v;
}

// ---------------------------------------------------------------------------
// Launch
// ---------------------------------------------------------------------------
extern "C" void kernel_launch(void* const* d_in, const int* in_sizes, int n_in,
                              void* d_out, int out_size)
{
    (void)in_sizes; (void)n_in; (void)out_size;

    const float* x    = (const float*)d_in[0];
    const float* done = (const float*)d_in[1];
    const float* h0   = (const float*)d_in[2];
    const float* c0   = (const float*)d_in[3];
    const float* Wih  = (const float*)d_in[4];
    const float* Whh  = (const float*)d_in[5];
    const float* bih  = (const float*)d_in[6];
    const float* bhh  = (const float*)d_in[7];
    const float* Wp1  = (const float*)d_in[8];
    const float* bp1  = (const float*)d_in[9];
    const float* Wp2  = (const float*)d_in[10];
    const float* bp2  = (const float*)d_in[11];
    const float* Wv1  = (const float*)d_in[12];
    const float* bv1  = (const float*)d_in[13];
    const float* Wv2  = (const float*)d_in[14];
    const float* bv2  = (const float*)d_in[15];

    float* out = (float*)d_out;
    float* hT  = out + (size_t)T_ * B_ * (A_ + 1);   // after [T*B, 9]
    float* cT  = hT + (size_t)B_ * H_;

    const int lstm_smem  = 51456 * 4;   // 205824 B
    const int heads_smem = 50112 * 4;   // 200448 B
    cudaFuncSetAttribute(lstm_kernel,  cudaFuncAttributeMaxDynamicSharedMemorySize, lstm_smem);
    cudaFuncSetAttribute(heads_kernel, cudaFuncAttributeMaxDynamicSharedMemorySize, heads_smem);

    // 1) input projection: 1024 m-tiles x 4 n-tiles (double-buffered)
    gemm_xw_kernel<<<4096, 256>>>(x, Wih, bih, bhh);
    // 2) recurrence: 128 persistent blocks (2 batch rows each, xg prefetch)
    lstm_kernel<<<128, 512, lstm_smem>>>(done, h0, c0, Whh, hT, cT);
    // 3) heads: 512 blocks x 256 rows
    heads_kernel<<<512, 256, heads_smem>>>(Wp1, bp1, Wp2, bp2, Wv1, bv1, Wv2, bv2, out);
}

// round 11
// speedup vs baseline: 1.9202x; 1.1603x over previous
#include <cuda_runtime.h>

// Problem dims (fixed)
#define T_  512
#define B_  256
#define F_  512
#define H_  128
#define G4_ 512   // 4*H
#define A_  8
#define MH_ 64

// Scratch (allocation-free rule: __device__ globals)
__device__ float g_xgates[(size_t)T_ * B_ * G4_];  // x @ W_ih^T + biases
__device__ float g_hseq[(size_t)T_ * B_ * H_];     // per-step hidden states

// ---------------------------------------------------------------------------
// Fast activations (fp32, ~1e-6 rel err)
// ---------------------------------------------------------------------------
__device__ __forceinline__ float sigm_f(float x) {
    return 1.0f / (1.0f + __expf(-x));
}
__device__ __forceinline__ float tanh_f(float x) {
    float e = __expf(2.0f * x);
    return 1.0f - 2.0f / (e + 1.0f);
}

// ---------------------------------------------------------------------------
// Kernel 1: xgates = X[131072,512] @ W_ih^T[512,512] + (b_ih + b_hh)
// 128x128x16 tiled SGEMM, double-buffered (R10 version, unchanged).
// ---------------------------------------------------------------------------
#define KT 16
__global__ __launch_bounds__(256, 2)
void gemm_xw_kernel(const float* __restrict__ X,
                    const float* __restrict__ Wih,
                    const float* __restrict__ bih,
                    const float* __restrict__ bhh)
{
    __shared__ float As[2][KT * 128];
    __shared__ float Bs[2][KT * 128];

    const int tid = threadIdx.x;
    const int bm  = blockIdx.x >> 2;
    const int bn  = blockIdx.x & 3;
    const int m0  = bm * 128;
    const int g0  = bn * 128;

    const int tm = tid >> 4;
    const int tn = tid & 15;

    const int lrow = tid >> 1;
    const int lk   = (tid & 1) * 8;

    const float* Xp = X   + (size_t)(m0 + lrow) * F_ + lk;
    const float* Wp = Wih + (size_t)(g0 + lrow) * F_ + lk;

    float acc[8][8];
#pragma unroll
    for (int i = 0; i < 8; i++)
#pragma unroll
        for (int j = 0; j < 8; j++) acc[i][j] = 0.0f;

    float bias[8];
#pragma unroll
    for (int j = 0; j < 8; j++) {
        int g = g0 + tn * 8 + j;
        bias[j] = bih[g] + bhh[g];
    }

    float4 ra0 = *reinterpret_cast<const float4*>(Xp);
    float4 ra1 = *reinterpret_cast<const float4*>(Xp + 4);
    float4 rb0 = *reinterpret_cast<const float4*>(Wp);
    float4 rb1 = *reinterpret_cast<const float4*>(Wp + 4);
    {
        float av[8] = {ra0.x, ra0.y, ra0.z, ra0.w, ra1.x, ra1.y, ra1.z, ra1.w};
        float bv[8] = {rb0.x, rb0.y, rb0.z, rb0.w, rb1.x, rb1.y, rb1.z, rb1.w};
#pragma unroll
        for (int q = 0; q < 8; q++) {
            As[0][(lk + q) * 128 + lrow] = av[q];
            Bs[0][(lk + q) * 128 + lrow] = bv[q];
        }
    }
    __syncthreads();

    const int NT = F_ / KT;
#pragma unroll 1
    for (int kt = 0; kt < NT; kt++) {
        const int cur = kt & 1;

        if (kt + 1 < NT) {
            const float* xn = Xp + (kt + 1) * KT;
            const float* wn = Wp + (kt + 1) * KT;
            ra0 = *reinterpret_cast<const float4*>(xn);
            ra1 = *reinterpret_cast<const float4*>(xn + 4);
            rb0 = *reinterpret_cast<const float4*>(wn);
            rb1 = *reinterpret_cast<const float4*>(wn + 4);
        }

        const float* Ac = As[cur];
        const float* Bc = Bs[cur];
#pragma unroll
        for (int k = 0; k < KT; k++) {
            float a[8], b[8];
            float4 a0 = *reinterpret_cast<const float4*>(Ac + k * 128 + tm * 8);
            float4 a1 = *reinterpret_cast<const float4*>(Ac + k * 128 + tm * 8 + 4);
            float4 b0 = *reinterpret_cast<const float4*>(Bc + k * 128 + tn * 8);
            float4 b1 = *reinterpret_cast<const float4*>(Bc + k * 128 + tn * 8 + 4);
            a[0]=a0.x; a[1]=a0.y; a[2]=a0.z; a[3]=a0.w; a[4]=a1.x; a[5]=a1.y; a[6]=a1.z; a[7]=a1.w;
            b[0]=b0.x; b[1]=b0.y; b[2]=b0.z; b[3]=b0.w; b[4]=b1.x; b[5]=b1.y; b[6]=b1.z; b[7]=b1.w;
#pragma unroll
            for (int i = 0; i < 8; i++)
#pragma unroll
                for (int j = 0; j < 8; j++)
                    acc[i][j] = fmaf(a[i], b[j], acc[i][j]);
        }

        if (kt + 1 < NT) {
            const int nxt = cur ^ 1;
            float av[8] = {ra0.x, ra0.y, ra0.z, ra0.w, ra1.x, ra1.y, ra1.z, ra1.w};
            float bv[8] = {rb0.x, rb0.y, rb0.z, rb0.w, rb1.x, rb1.y, rb1.z, rb1.w};
#pragma unroll
            for (int q = 0; q < 8; q++) {
                As[nxt][(lk + q) * 128 + lrow] = av[q];
                Bs[nxt][(lk + q) * 128 + lrow] = bv[q];
            }
        }
        __syncthreads();
    }

#pragma unroll
    for (int i = 0; i < 8; i++) {
        int m = m0 + tm * 8 + i;
        float4 o0 = make_float4(acc[i][0] + bias[0], acc[i][1] + bias[1],
                                acc[i][2] + bias[2], acc[i][3] + bias[3]);
        float4 o1 = make_float4(acc[i][4] + bias[4], acc[i][5] + bias[5],
                                acc[i][6] + bias[6], acc[i][7] + bias[7]);
        float* dst = g_xgates + (size_t)m * G4_ + g0 + tn * 8;
        *reinterpret_cast<float4*>(dst)     = o0;
        *reinterpret_cast<float4*>(dst + 4) = o1;
    }
}

// ---------------------------------------------------------------------------
// Kernel 2: persistent masked-LSTM recurrence — FAT-THREAD layout.
// Grid = 128 blocks x 256 threads; block owns batch rows {2*bx, 2*bx+1}.
// Thread tid computes gates g0=tid and g1=tid+256 for BOTH rows, so each h
// broadcast LDS feeds 2 gates' FMAs (h crossbar wavefronts halved vs R5) and
// 160 registers hold W_hh cols 0..79 for both gates (W smem shrinks to 48
// cols -> W wavefronts cut ~2x). Step B now uses all 256 threads.
//
// Dynamic smem (floats):
//   [0     , 24576) Wsm4 : float4[12*512], Wsm4[k4*512+g] = W_hh[g][80+4k4..+3]
//   [24576 , 25600) done_s[1024]  (t-major, 2 rows)
//   [25600 , 25856) h_s[2][128]
//   [25856 , 26880) gs [2][512]
// total = 26880 floats = 107520 bytes
// ---------------------------------------------------------------------------
#define KREG 80              // W cols in registers (per gate)
#define KR4  (KREG / 4)      // 20
#define KS4  ((H_ - KREG)/4) // 12 smem float4 cols

__global__ __launch_bounds__(256, 1)
void lstm_kernel(const float* __restrict__ done,
                 const float* __restrict__ h0,
                 const float* __restrict__ c0,
                 const float* __restrict__ Whh,
                 float* __restrict__ hT,
                 float* __restrict__ cT)
{
    extern __shared__ float sm[];
    float4* Wsm4   = reinterpret_cast<float4*>(sm);   // [KS4*512]
    float*  done_s = sm + 24576;                      // [1024]
    float*  h_s    = sm + 25600;                      // [2][128]
    float*  gs     = sm + 25856;                      // [2][512]

    const int tid = threadIdx.x;
    const int g0  = tid;         // first gate row
    const int g1  = tid + 256;   // second gate row
    const int b0  = blockIdx.x * 2;

    // Register W: cols 0..KREG-1 for both gates
    float W0[KREG], W1[KREG];
    {
        const float4* wr0 = reinterpret_cast<const float4*>(Whh + (size_t)g0 * H_);
        const float4* wr1 = reinterpret_cast<const float4*>(Whh + (size_t)g1 * H_);
#pragma unroll
        for (int k4 = 0; k4 < KR4; k4++) {
            float4 a = wr0[k4];
            W0[4*k4+0] = a.x; W0[4*k4+1] = a.y; W0[4*k4+2] = a.z; W0[4*k4+3] = a.w;
            float4 b = wr1[k4];
            W1[4*k4+0] = b.x; W1[4*k4+1] = b.y; W1[4*k4+2] = b.z; W1[4*k4+3] = b.w;
        }
        // Smem W: cols KREG..127 for both gate rows
#pragma unroll
        for (int k4 = 0; k4 < KS4; k4++) {
            Wsm4[k4 * 512 + g0] = wr0[KR4 + k4];
            Wsm4[k4 * 512 + g1] = wr1[KR4 + k4];
        }
    }
    // done-mask preload (t-major, 2 rows)
    for (int idx = tid; idx < 2 * T_; idx += 256) {
        int t = idx >> 1, bi2 = idx & 1;
        done_s[idx] = done[(size_t)t * B_ + b0 + bi2];
    }

    // Per-(b,j) state: thread = (bi, j)
    const int bi = tid >> 7;
    const int j  = tid & 127;
    float creg;
    {
        float hreg = h0[(size_t)(b0 + bi) * H_ + j];
        creg = c0[(size_t)(b0 + bi) * H_ + j];
        float m = 1.0f - done_s[bi];
        creg *= m;
        h_s[bi * 128 + j] = hreg * m;
    }
    __syncthreads();

    const float4* h0v = reinterpret_cast<const float4*>(h_s);
    const float4* h1v = reinterpret_cast<const float4*>(h_s + 128);

    // xg for current step (4 values: 2 gates x 2 rows), prefetched one step ahead
    const size_t step_stride = (size_t)B_ * G4_;
    const float* xg_base = g_xgates + (size_t)b0 * G4_;
    float xg00 = xg_base[g0];
    float xg01 = xg_base[G4_ + g0];
    float xg10 = xg_base[g1];
    float xg11 = xg_base[G4_ + g1];

    float hfin = 0.0f;

#pragma unroll 1
    for (int t = 0; t < T_; t++) {
        // prefetch next step's xg (consumed a full step later)
        const int tnx = (t + 1 < T_) ? (t + 1) : t;
        const float* xn = xg_base + (size_t)tnx * step_stride;
        float nx00 = xn[g0];
        float nx01 = xn[G4_ + g0];
        float nx10 = xn[g1];
        float nx11 = xn[G4_ + g1];

        // ---- Step A: 4 dot products (2 gates x 2 rows), h reused across gates
        {
            float a00 = 0.0f, b00 = 0.0f;   // gate0, row0
            float a01 = 0.0f, b01 = 0.0f;   // gate0, row1
            float a10 = 0.0f, b10 = 0.0f;   // gate1, row0
            float a11 = 0.0f, b11 = 0.0f;   // gate1, row1

            // register-W part (cols 0..KREG-1)
#pragma unroll
            for (int k4 = 0; k4 < KR4; k4++) {
                float4 ha = h0v[k4];
                float4 hb = h1v[k4];
                a00 = fmaf(W0[4*k4+0], ha.x, a00);
                b00 = fmaf(W0[4*k4+1], ha.y, b00);
                a00 = fmaf(W0[4*k4+2], ha.z, a00);
                b00 = fmaf(W0[4*k4+3], ha.w, b00);
                a01 = fmaf(W0[4*k4+0], hb.x, a01);
                b01 = fmaf(W0[4*k4+1], hb.y, b01);
                a01 = fmaf(W0[4*k4+2], hb.z, a01);
                b01 = fmaf(W0[4*k4+3], hb.w, b01);
                a10 = fmaf(W1[4*k4+0], ha.x, a10);
                b10 = fmaf(W1[4*k4+1], ha.y, b10);
                a10 = fmaf(W1[4*k4+2], ha.z, a10);
                b10 = fmaf(W1[4*k4+3], ha.w, b10);
                a11 = fmaf(W1[4*k4+0], hb.x, a11);
                b11 = fmaf(W1[4*k4+1], hb.y, b11);
                a11 = fmaf(W1[4*k4+2], hb.z, a11);
                b11 = fmaf(W1[4*k4+3], hb.w, b11);
            }
            // smem-W part (cols KREG..127)
#pragma unroll 4
            for (int k4 = 0; k4 < KS4; k4++) {
                float4 w0 = Wsm4[k4 * 512 + g0];
                float4 w1 = Wsm4[k4 * 512 + g1];
                float4 ha = h0v[KR4 + k4];
                float4 hb = h1v[KR4 + k4];
                a00 = fmaf(w0.x, ha.x, a00);
                b00 = fmaf(w0.y, ha.y, b00);
                a00 = fmaf(w0.z, ha.z, a00);
                b00 = fmaf(w0.w, ha.w, b00);
                a01 = fmaf(w0.x, hb.x, a01);
                b01 = fmaf(w0.y, hb.y, b01);
                a01 = fmaf(w0.z, hb.z, a01);
                b01 = fmaf(w0.w, hb.w, b01);
                a10 = fmaf(w1.x, ha.x, a10);
                b10 = fmaf(w1.y, ha.y, b10);
                a10 = fmaf(w1.z, ha.z, a10);
                b10 = fmaf(w1.w, ha.w, b10);
                a11 = fmaf(w1.x, hb.x, a11);
                b11 = fmaf(w1.y, hb.y, b11);
                a11 = fmaf(w1.z, hb.z, a11);
                b11 = fmaf(w1.w, hb.w, b11);
            }
            gs[g0]        = a00 + b00 + xg00;
            gs[512 + g0]  = a01 + b01 + xg01;
            gs[g1]        = a10 + b10 + xg10;
            gs[512 + g1]  = a11 + b11 + xg11;
        }
        __syncthreads();

        // rotate prefetched xg
        xg00 = nx00; xg01 = nx01; xg10 = nx10; xg11 = nx11;

        // ---- Step B: nonlinearities + state update (all 256 threads active)
        {
            float gi = gs[bi * 512 +        j];
            float gf = gs[bi * 512 + 128 + j];
            float gg = gs[bi * 512 + 256 + j];
            float go = gs[bi * 512 + 384 + j];
            float iv = sigm_f(gi);
            float fv = sigm_f(gf);
            float gv = tanh_f(gg);
            float ov = sigm_f(go);
            creg = fmaf(fv, creg, iv * gv);
            float hv = ov * tanh_f(creg);
            g_hseq[((size_t)t * B_ + b0 + bi) * H_ + j] = hv;
            if (t + 1 < T_) {
                float m = 1.0f - done_s[(t + 1) * 2 + bi];
                creg *= m;
                h_s[bi * 128 + j] = hv * m;
            } else {
                hfin = hv;
            }
        }
        __syncthreads();
    }

    hT[(size_t)(b0 + bi) * H_ + j] = hfin;
    cT[(size_t)(b0 + bi) * H_ + j] = creg;
}

// ---------------------------------------------------------------------------
// Kernel 3: heads (unchanged, known good).
// ---------------------------------------------------------------------------
__global__ __launch_bounds__(256, 1)
void heads_kernel(const float* __restrict__ Wp1, const float* __restrict__ bp1,
                  const float* __restrict__ Wp2, const float* __restrict__ bp2,
                  const float* __restrict__ Wv1, const float* __restrict__ bv1,
                  const float* __restrict__ Wv2, const float* __restrict__ bv2,
                  float* __restrict__ out)
{
    extern __shared__ float sm[];
    float* h_s  = sm;            // [256][129]
    float* wp1  = sm + 33024;
    float* wv1  = sm + 41216;
    float* wp2  = sm + 49408;
    float* wv2  = sm + 49920;
    float* sbp1 = sm + 49984;
    float* sbv1 = sm + 50048;

    const int tid = threadIdx.x;
    const size_t row0 = (size_t)blockIdx.x * 256;

    for (int idx = tid; idx < 256 * 32; idx += 256) {
        int r  = idx >> 5;
        int c4 = idx & 31;
        float4 v = reinterpret_cast<const float4*>(g_hseq + (row0 + r) * H_)[c4];
        float* dst = h_s + r * 129 + c4 * 4;
        dst[0] = v.x; dst[1] = v.y; dst[2] = v.z; dst[3] = v.w;
    }
    for (int idx = tid; idx < H_ * MH_; idx += 256) {
        wp1[idx] = Wp1[idx];
        wv1[idx] = Wv1[idx];
    }
    for (int idx = tid; idx < MH_ * A_; idx += 256) wp2[idx] = Wp2[idx];
    if (tid < 64) {
        wv2[tid]  = Wv2[tid];
        sbp1[tid] = bp1[tid];
        sbv1[tid] = bv1[tid];
    }
    __syncthreads();

    float ap[64], av[64];
#pragma unroll
    for (int i = 0; i < 64; i++) { ap[i] = 0.0f; av[i] = 0.0f; }

    const float*  hrow = h_s + tid * 129;
    const float4* wp1v = reinterpret_cast<const float4*>(wp1);
    const float4* wv1v = reinterpret_cast<const float4*>(wv1);

#pragma unroll 1
    for (int k = 0; k < H_; k++) {
        float hk = hrow[k];
#pragma unroll
        for (int m4 = 0; m4 < 16; m4++) {
            float4 wp = wp1v[k * 16 + m4];
            float4 wv = wv1v[k * 16 + m4];
            ap[m4 * 4 + 0] = fmaf(hk, wp.x, ap[m4 * 4 + 0]);
            ap[m4 * 4 + 1] = fmaf(hk, wp.y, ap[m4 * 4 + 1]);
            ap[m4 * 4 + 2] = fmaf(hk, wp.z, ap[m4 * 4 + 2]);
            ap[m4 * 4 + 3] = fmaf(hk, wp.w, ap[m4 * 4 + 3]);
            av[m4 * 4 + 0] = fmaf(hk, wv.x, av[m4 * 4 + 0]);
            av[m4 * 4 + 1] = fmaf(hk, wv.y, av[m4 * 4 + 1]);
            av[m4 * 4 + 2] = fmaf(hk, wv.z, av[m4 * 4 + 2]);
            av[m4 * 4 + 3] = fmaf(hk, wv.w, av[m4 * 4 + 3]);
        }
    }

    float lg[8];
#pragma unroll
    for (int a = 0; a < 8; a++) lg[a] = bp2[a];
    float v = bv2[0];

#pragma unroll
    for (int mh = 0; mh < 64; mh++) {
        float tp = tanh_f(ap[mh] + sbp1[mh]);
        float tv = tanh_f(av[mh] + sbv1[mh]);
        v = fmaf(tv, wv2[mh], v);
#pragma unroll
        for (int a = 0; a < 8; a++)
            lg[a] = fmaf(tp, wp2[mh * 8 + a], lg[a]);
    }

    float* orow = out + (row0 + tid) * 9;
#pragma unroll
    for (int a = 0; a < 8; a++) orow[a] = lg[a];
    orow[8] = v;
}

// ---------------------------------------------------------------------------
// Launch
// ---------------------------------------------------------------------------
extern "C" void kernel_launch(void* const* d_in, const int* in_sizes, int n_in,
                              void* d_out, int out_size)
{
    (void)in_sizes; (void)n_in; (void)out_size;

    const float* x    = (const float*)d_in[0];
    const float* done = (const float*)d_in[1];
    const float* h0   = (const float*)d_in[2];
    const float* c0   = (const float*)d_in[3];
    const float* Wih  = (const float*)d_in[4];
    const float* Whh  = (const float*)d_in[5];
    const float* bih  = (const float*)d_in[6];
    const float* bhh  = (const float*)d_in[7];
    const float* Wp1  = (const float*)d_in[8];
    const float* bp1  = (const float*)d_in[9];
    const float* Wp2  = (const float*)d_in[10];
    const float* bp2  = (const float*)d_in[11];
    const float* Wv1  = (const float*)d_in[12];
    const float* bv1  = (const float*)d_in[13];
    const float* Wv2  = (const float*)d_in[14];
    const float* bv2  = (const float*)d_in[15];

    float* out = (float*)d_out;
    float* hT  = out + (size_t)T_ * B_ * (A_ + 1);   // after [T*B, 9]
    float* cT  = hT + (size_t)B_ * H_;

    const int lstm_smem  = 26880 * 4;   // 107520 B
    const int heads_smem = 50112 * 4;   // 200448 B
    cudaFuncSetAttribute(lstm_kernel,  cudaFuncAttributeMaxDynamicSharedMemorySize, lstm_smem);
    cudaFuncSetAttribute(heads_kernel, cudaFuncAttributeMaxDynamicSharedMemorySize, heads_smem);

    // 1) input projection: 1024 m-tiles x 4 n-tiles (double-buffered)
    gemm_xw_kernel<<<4096, 256>>>(x, Wih, bih, bhh);
    // 2) recurrence: 128 persistent blocks, 256 fat threads (2 gates each)
    lstm_kernel<<<128, 256, lstm_smem>>>(done, h0, c0, Whh, hT, cT);
    // 3) heads: 512 blocks x 256 rows
    heads_kernel<<<512, 256, heads_smem>>>(Wp1, bp1, Wp2, bp2, Wv1, bv1, Wv2, bv2, out);
}